// round 4
// baseline (speedup 1.0000x reference)
#include <cuda_runtime.h>
#include <cstdint>

// Problem constants
#define Qn 4
#define Kc 2048
#define Dd 256
#define Bb 8
#define Nn 8192
#define NTOK (Bb * Nn)        // 65536 tokens
#define MCHUNK (Nn / Qn)      // 2048 tokens per (b, q) chunk

// Tiling
#define TM 128                // tokens per block
#define TN 128                // codes per k-tile
#define DC 32                 // d-depth per pipeline stage
#define NKT (Kc / TN)         // 16 k-tiles
#define NDCH (Dd / DC)        // 8 d-chunks per k-tile
#define NSTAGE (NKT * NDCH)   // 128 stages

// Shared memory layout (floats)
#define XS_FLOATS (Dd * TM)           // 32768  (128 KB)  Xs[d][token]
#define ES_FLOATS (2 * DC * TN * 2)   // 16384  (64 KB)   double-buffered, pair-duplicated E tile
#define SMEM_FLOATS (XS_FLOATS + ES_FLOATS)   // 49152 floats = 192 KB

// Normalized tensors, replicating the reference's fp32 rounding pipeline.
__device__ float g_en[Qn * Kc * Dd];     // 8 MB
__device__ float g_xn[NTOK * Dd];        // 64 MB

// ---------------------------------------------------------------------------
// Kernel 0: row-wise L2 normalize, emulating XLA GPU's row-reduce order:
//   per-lane partial over elements [lane + 32*i], UNFUSED mul+add (no FMA),
//   shfl.down pairwise tree, sqrt.rn, max(norm,1e-12), div.rn per element.
// One warp per 256-float row.
// ---------------------------------------------------------------------------
__global__ void l2norm_rows_kernel(const float* __restrict__ src,
                                   float* __restrict__ dst,
                                   int nrows) {
    int row  = blockIdx.x * 8 + (threadIdx.x >> 5);
    int lane = threadIdx.x & 31;
    if (row >= nrows) return;
    const float* r = src + (size_t)row * Dd;
    float v[8];
    float s = 0.f;
#pragma unroll
    for (int i = 0; i < 8; ++i) {
        v[i] = r[lane + 32 * i];
        s = __fadd_rn(s, __fmul_rn(v[i], v[i]));   // no contraction
    }
#pragma unroll
    for (int o = 16; o; o >>= 1)
        s = __fadd_rn(s, __shfl_down_sync(0xffffffffu, s, o));
    float total = __shfl_sync(0xffffffffu, s, 0);
    float nf = fmaxf(__fsqrt_rn(total), 1e-12f);
    float* w = dst + (size_t)row * Dd;
#pragma unroll
    for (int i = 0; i < 8; ++i)
        w[lane + 32 * i] = __fdiv_rn(v[i], nf);
}

// Packed fp32x2 FMA (sm_100+): 2 FMAs per instruction, same issue rate as FFMA.
// Each half rounds identically to a scalar FFMA -> bit-equal to a sequential
// ascending-k FFMA chain (cuBLAS / Eigen per-element accumulation order).
__device__ __forceinline__ void ffma2(unsigned long long& d,
                                      unsigned long long a,
                                      unsigned long long b) {
    asm("fma.rn.f32x2 %0, %1, %2, %0;" : "+l"(d) : "l"(a), "l"(b));
}

// ---------------------------------------------------------------------------
// Kernel 1: fused cosine GEMM + argmax + gather.
// Block = 128 tokens (one quantizer), 256 threads, 8x8 microtile per thread
// with token-pair packing for f32x2. Inputs are pre-normalized (g_xn, g_en).
// ---------------------------------------------------------------------------
__global__ void __launch_bounds__(256, 1)
pq_kernel(const float* __restrict__ embed,
          float* __restrict__ out,
          long long out_size) {
    extern __shared__ float smem[];
    float* Xs = smem;                 // [256][128]  xn[d][token]
    float* Es = smem + XS_FLOATS;     // [2][32][128*2] (duplicated pairs)

    const int tid = threadIdx.x;
    const int tx  = tid & 15;           // code dim (16)
    const int ty  = tid >> 4;           // token dim (16)
    const int tok0 = blockIdx.x * TM;
    const int q = (tok0 % Nn) / MCHUNK;
    const float* Eqn   = g_en  + (size_t)q * Kc * Dd;   // normalized, for scoring
    const float* Eqraw = embed + (size_t)q * Kc * Dd;   // raw, for gather

    // stage normalized X tile transposed: Xs[d][token]
    for (int i = tid; i < TM * (Dd / 4); i += 256) {
        int token = i & (TM - 1);
        int rb    = i >> 7;            // float4 index along d: 0..63
        float4 v = ((const float4*)(g_xn + (size_t)(tok0 + token) * Dd))[rb];
        Xs[(rb * 4 + 0) * TM + token] = v.x;
        Xs[(rb * 4 + 1) * TM + token] = v.y;
        Xs[(rb * 4 + 2) * TM + token] = v.z;
        Xs[(rb * 4 + 3) * TM + token] = v.w;
    }

    float4 rg[4];
    // prologue: ldg stage 0 of the normalized codebook
    {
#pragma unroll
        for (int r = 0; r < 4; ++r) {
            int f = tid * 4 + r;
            int j = f >> 3;
            int dpos = (f & 7) * 4;
            rg[r] = *(const float4*)(Eqn + (size_t)j * Dd + dpos);
        }
    }
    // sts stage 0 -> buf 0 (duplicated pairs); Es untouched by X staging
    {
#pragma unroll
        for (int r = 0; r < 4; ++r) {
            int f = tid * 4 + r;
            int j = f >> 3;
            int dpos = (f & 7) * 4;
            float vv[4] = {rg[r].x, rg[r].y, rg[r].z, rg[r].w};
#pragma unroll
            for (int c = 0; c < 4; ++c) {
                *(float2*)(Es + (dpos + c) * (TN * 2) + j * 2) = make_float2(vv[c], vv[c]);
            }
        }
    }

    // accumulators: 4 token-pairs x 8 codes, packed f32x2
    unsigned long long acc[4][8];
#pragma unroll
    for (int ip = 0; ip < 4; ++ip)
#pragma unroll
        for (int jc = 0; jc < 8; ++jc) acc[ip][jc] = 0ull;

    // per-slot argmax (codes visited ascending per slot; strict > keeps lowest)
    float bv[8];
    int   bi[8];
#pragma unroll
    for (int t = 0; t < 8; ++t) { bv[t] = -3.4e38f; bi[t] = 0x7fffffff; }

    for (int s = 0; s < NSTAGE; ++s) {
        const int buf = s & 1;

        // prefetch next stage (global -> regs)
        if (s + 1 < NSTAGE) {
            const int kt = (s + 1) >> 3;
            const int dc = (s + 1) & (NDCH - 1);
#pragma unroll
            for (int r = 0; r < 4; ++r) {
                int f = tid * 4 + r;
                int j = f >> 3;
                int dpos = (f & 7) * 4;
                rg[r] = *(const float4*)(Eqn + (size_t)(kt * TN + j) * Dd + dc * DC + dpos);
            }
        }

        __syncthreads();   // current buf visible (also covers Xs staging at s=0)

        // compute 32 d-steps from buf (ascending d => sequential FFMA chain)
        const int dcBase = (s & (NDCH - 1)) * DC;
        const float* Eb = Es + buf * (DC * TN * 2);
#pragma unroll 8
        for (int dd = 0; dd < DC; ++dd) {
            const int dg = dcBase + dd;
            ulonglong2 a01 = *(const ulonglong2*)&Xs[dg * TM + ty * 8];
            ulonglong2 a23 = *(const ulonglong2*)&Xs[dg * TM + ty * 8 + 4];
            const ulonglong2* bp = (const ulonglong2*)(Eb + dd * (TN * 2) + tx * 16);
            ulonglong2 b0 = bp[0], b1 = bp[1], b2 = bp[2], b3 = bp[3];
            unsigned long long A[4]  = {a01.x, a01.y, a23.x, a23.y};
            unsigned long long Bv[8] = {b0.x, b0.y, b1.x, b1.y, b2.x, b2.y, b3.x, b3.y};
#pragma unroll
            for (int ip = 0; ip < 4; ++ip)
#pragma unroll
                for (int jc = 0; jc < 8; ++jc) ffma2(acc[ip][jc], A[ip], Bv[jc]);
        }

        // k-tile complete: fold scores into running argmax, reset accumulators
        if ((s & (NDCH - 1)) == NDCH - 1) {
            const int kt = s >> 3;
#pragma unroll
            for (int jc = 0; jc < 8; ++jc) {
                const int code = kt * TN + tx * 8 + jc;
#pragma unroll
                for (int ip = 0; ip < 4; ++ip) {
                    float s0 = __uint_as_float((unsigned)(acc[ip][jc] & 0xffffffffull));
                    float s1 = __uint_as_float((unsigned)(acc[ip][jc] >> 32));
                    int t0 = ip * 2, t1 = ip * 2 + 1;
                    if (s0 > bv[t0]) { bv[t0] = s0; bi[t0] = code; }
                    if (s1 > bv[t1]) { bv[t1] = s1; bi[t1] = code; }
                    acc[ip][jc] = 0ull;
                }
            }
        }

        __syncthreads();   // everyone done reading buf^1 before overwrite

        if (s + 1 < NSTAGE) {
#pragma unroll
            for (int r = 0; r < 4; ++r) {
                int f = tid * 4 + r;
                int j = f >> 3;
                int dpos = (f & 7) * 4;
                float* base = Es + ((s + 1) & 1) * (DC * TN * 2);
                float vv[4] = {rg[r].x, rg[r].y, rg[r].z, rg[r].w};
#pragma unroll
                for (int c = 0; c < 4; ++c) {
                    *(float2*)(base + (dpos + c) * (TN * 2) + j * 2) = make_float2(vv[c], vv[c]);
                }
            }
        }
    }

    // ---- cross-thread argmax reduction (reuse Es area) ----
    __syncthreads();
    float* rv = Es;                        // [128][16]
    int*   ri = (int*)(Es + TM * 16);      // [128][16]
    int*   bestcode = (int*)(Es + TM * 16 * 2);  // [128]
#pragma unroll
    for (int t = 0; t < 8; ++t) {
        rv[(ty * 8 + t) * 16 + tx] = bv[t];
        ri[(ty * 8 + t) * 16 + tx] = bi[t];
    }
    __syncthreads();
    if (tid < TM) {
        float best = -3.4e38f;
        int bidx = 0x7fffffff;
#pragma unroll
        for (int j = 0; j < 16; ++j) {
            float v = rv[tid * 16 + j];
            int   c = ri[tid * 16 + j];
            // exact-tie: lowest code index wins (matches jnp.argmax)
            if (v > best || (v == best && c < bidx)) { best = v; bidx = c; }
        }
        bestcode[tid] = bidx;
        long long epos = (long long)NTOK * Dd + (tok0 + tid);
        if (epos < out_size) out[epos] = (float)bidx;   // encoding as float
    }
    __syncthreads();

    // ---- gather raw codewords into quantized output (coalesced) ----
    for (int i = tid; i < TM * (Dd / 4); i += 256) {
        int token = i >> 6;     // 64 float4 per token
        int r = i & 63;
        int code = bestcode[token];
        ((float4*)(out + (size_t)(tok0 + token) * Dd))[r] =
            ((const float4*)(Eqraw + (size_t)code * Dd))[r];
    }
}

// ---------------------------------------------------------------------------
// Tail: zero-fill vq_loss (and any slack) past quantized+encoding.
// ---------------------------------------------------------------------------
__global__ void zero_tail(float* __restrict__ out, long long start, long long end) {
    long long i = start + (long long)blockIdx.x * blockDim.x + threadIdx.x;
    if (i < end) out[i] = 0.f;
}

extern "C" void kernel_launch(void* const* d_in, const int* in_sizes, int n_in,
                              void* d_out, int out_size) {
    const float* x     = (const float*)d_in[0];
    const float* embed = (const float*)d_in[1];
    // robustness: identify inputs by size if order differs
    if (n_in >= 2 && in_sizes[0] == Qn * Kc * Dd && in_sizes[1] == NTOK * Dd) {
        const float* t = x; x = embed; embed = t;
    }
    float* out = (float*)d_out;

    // Normalize embed and x rows with reference-mimicking fp32 pipeline.
    {
        float* en_ptr; cudaGetSymbolAddress((void**)&en_ptr, g_en);
        float* xn_ptr; cudaGetSymbolAddress((void**)&xn_ptr, g_xn);
        l2norm_rows_kernel<<<(Qn * Kc) / 8, 256>>>(embed, en_ptr, Qn * Kc);
        l2norm_rows_kernel<<<NTOK / 8, 256>>>(x, xn_ptr, NTOK);
    }

    cudaFuncSetAttribute(pq_kernel, cudaFuncAttributeMaxDynamicSharedMemorySize,
                         SMEM_FLOATS * sizeof(float));

    pq_kernel<<<NTOK / TM, 256, SMEM_FLOATS * sizeof(float)>>>(
        embed, out, (long long)out_size);

    long long tail = (long long)NTOK * Dd + NTOK;
    if ((long long)out_size > tail) {
        long long n = (long long)out_size - tail;
        int blocks = (int)((n + 255) / 256);
        zero_tail<<<blocks, 256>>>(out, tail, (long long)out_size);
    }
}

// round 5
// speedup vs baseline: 2.4062x; 2.4062x over previous
#include <cuda_runtime.h>
#include <cstdint>

// Problem constants
#define Qn 4
#define Kc 2048
#define Dd 256
#define Bb 8
#define Nn 8192
#define NTOK (Bb * Nn)        // 65536 tokens
#define MCHUNK (Nn / Qn)      // 2048 tokens per (b, q) chunk

// Tiling
#define TM 128                // tokens per block
#define TN 128                // codes per k-tile
#define DC 32                 // d-depth per pipeline stage
#define NKT (Kc / TN)         // 16 k-tiles
#define NDCH (Dd / DC)        // 8 d-chunks per k-tile
#define NSTAGE (NKT * NDCH)   // 128 stages

// Shared memory layout (floats)
#define XS_FLOATS (Dd * TM)           // 32768  (128 KB)  Xs[d][token]
#define ES_FLOATS (2 * DC * TN * 2)   // 16384  (64 KB)   double-buffered, pair-duplicated E tile
#define SMEM_FLOATS (XS_FLOATS + ES_FLOATS)   // 49152 floats = 192 KB

// Normalized tensors, replicating the reference's fp32 rounding pipeline.
__device__ float g_en[Qn * Kc * Dd];     // 8 MB
__device__ float g_xn[NTOK * Dd];        // 64 MB

// ---------------------------------------------------------------------------
// Kernel 0: row-wise L2 normalize, emulating XLA GPU's row-reduce order:
//   per-lane partial over elements [lane + 32*i], UNFUSED mul+add (no FMA),
//   shfl.down pairwise tree, sqrt.rn, max(norm,1e-12), div.rn per element.
// One warp per 256-float row.  (DO NOT CHANGE — bit-exact vs reference.)
// ---------------------------------------------------------------------------
__global__ void l2norm_rows_kernel(const float* __restrict__ src,
                                   float* __restrict__ dst,
                                   int nrows) {
    int row  = blockIdx.x * 8 + (threadIdx.x >> 5);
    int lane = threadIdx.x & 31;
    if (row >= nrows) return;
    const float* r = src + (size_t)row * Dd;
    float v[8];
    float s = 0.f;
#pragma unroll
    for (int i = 0; i < 8; ++i) {
        v[i] = r[lane + 32 * i];
        s = __fadd_rn(s, __fmul_rn(v[i], v[i]));   // no contraction
    }
#pragma unroll
    for (int o = 16; o; o >>= 1)
        s = __fadd_rn(s, __shfl_down_sync(0xffffffffu, s, o));
    float total = __shfl_sync(0xffffffffu, s, 0);
    float nf = fmaxf(__fsqrt_rn(total), 1e-12f);
    float* w = dst + (size_t)row * Dd;
#pragma unroll
    for (int i = 0; i < 8; ++i)
        w[lane + 32 * i] = __fdiv_rn(v[i], nf);
}

// Packed fp32x2 FMA (sm_100+): 2 FMAs per instruction, same issue rate as FFMA.
// Each half rounds identically to a scalar FFMA -> bit-equal to a sequential
// ascending-d FFMA chain.
__device__ __forceinline__ void ffma2(unsigned long long& d,
                                      unsigned long long a,
                                      unsigned long long b) {
    asm("fma.rn.f32x2 %0, %1, %2, %0;" : "+l"(d) : "l"(a), "l"(b));
}

// ---------------------------------------------------------------------------
// Kernel 1: fused cosine GEMM + argmax + gather.
// Block = 128 tokens (one quantizer), 256 threads, 8x8 microtile per thread
// with token-pair packing for f32x2. Inputs pre-normalized (g_xn, g_en).
// B-tile reads use a conflict-free interleave: thread tx reads 16B at
// r*256B + tx*16B (8 consecutive threads cover one full 128B bank row).
// ---------------------------------------------------------------------------
__global__ void __launch_bounds__(256, 1)
pq_kernel(const float* __restrict__ embed,
          float* __restrict__ out,
          long long out_size) {
    extern __shared__ float smem[];
    float* Xs = smem;                 // [256][128]  xn[d][token]
    float* Es = smem + XS_FLOATS;     // [2][32][128*2] (duplicated pairs)

    const int tid = threadIdx.x;
    const int tx  = tid & 15;           // code dim (16)
    const int ty  = tid >> 4;           // token dim (16)
    const int tok0 = blockIdx.x * TM;
    const int q = (tok0 % Nn) / MCHUNK;
    const float* Eqn   = g_en  + (size_t)q * Kc * Dd;   // normalized, for scoring
    const float* Eqraw = embed + (size_t)q * Kc * Dd;   // raw, for gather

    // stage normalized X tile transposed: Xs[d][token]
    for (int i = tid; i < TM * (Dd / 4); i += 256) {
        int token = i & (TM - 1);
        int rb    = i >> 7;            // float4 index along d: 0..63
        float4 v = ((const float4*)(g_xn + (size_t)(tok0 + token) * Dd))[rb];
        Xs[(rb * 4 + 0) * TM + token] = v.x;
        Xs[(rb * 4 + 1) * TM + token] = v.y;
        Xs[(rb * 4 + 2) * TM + token] = v.z;
        Xs[(rb * 4 + 3) * TM + token] = v.w;
    }

    float4 rg[4];
    // prologue: ldg stage 0 of the normalized codebook
    {
#pragma unroll
        for (int r = 0; r < 4; ++r) {
            int f = tid * 4 + r;
            int j = f >> 3;
            int dpos = (f & 7) * 4;
            rg[r] = *(const float4*)(Eqn + (size_t)j * Dd + dpos);
        }
    }
    // sts stage 0 -> buf 0 (duplicated pairs: pair j at floats {2j, 2j+1})
    {
#pragma unroll
        for (int r = 0; r < 4; ++r) {
            int f = tid * 4 + r;
            int j = f >> 3;
            int dpos = (f & 7) * 4;
            float vv[4] = {rg[r].x, rg[r].y, rg[r].z, rg[r].w};
#pragma unroll
            for (int c = 0; c < 4; ++c) {
                *(float2*)(Es + (dpos + c) * (TN * 2) + j * 2) = make_float2(vv[c], vv[c]);
            }
        }
    }

    // accumulators: 4 token-pairs x 8 code-slots, packed f32x2
    unsigned long long acc[4][8];
#pragma unroll
    for (int ip = 0; ip < 4; ++ip)
#pragma unroll
        for (int jc = 0; jc < 8; ++jc) acc[ip][jc] = 0ull;

    // per-slot argmax (codes visited ascending per slot; strict > keeps lowest)
    float bv[8];
    int   bi[8];
#pragma unroll
    for (int t = 0; t < 8; ++t) { bv[t] = -3.4e38f; bi[t] = 0x7fffffff; }

    for (int s = 0; s < NSTAGE; ++s) {
        const int buf = s & 1;

        // prefetch next stage (global -> regs)
        if (s + 1 < NSTAGE) {
            const int kt = (s + 1) >> 3;
            const int dc = (s + 1) & (NDCH - 1);
#pragma unroll
            for (int r = 0; r < 4; ++r) {
                int f = tid * 4 + r;
                int j = f >> 3;
                int dpos = (f & 7) * 4;
                rg[r] = *(const float4*)(Eqn + (size_t)(kt * TN + j) * Dd + dc * DC + dpos);
            }
        }

        __syncthreads();   // current buf visible (also covers Xs staging at s=0)

        // compute 32 d-steps from buf (ascending d => sequential FFMA chain)
        const int dcBase = (s & (NDCH - 1)) * DC;
        const float* Eb = Es + buf * (DC * TN * 2);
#pragma unroll 8
        for (int dd = 0; dd < DC; ++dd) {
            const int dg = dcBase + dd;
            ulonglong2 a01 = *(const ulonglong2*)&Xs[dg * TM + ty * 8];
            ulonglong2 a23 = *(const ulonglong2*)&Xs[dg * TM + ty * 8 + 4];
            // Conflict-free interleave: read r at r*64 + tx*4 floats.
            // b_r.x = code (r*32 + tx*2) dup, b_r.y = code (r*32 + tx*2 + 1) dup.
            const float* Ebd = Eb + dd * (TN * 2);
            ulonglong2 b0 = *(const ulonglong2*)(Ebd + 0 * 64 + tx * 4);
            ulonglong2 b1 = *(const ulonglong2*)(Ebd + 1 * 64 + tx * 4);
            ulonglong2 b2 = *(const ulonglong2*)(Ebd + 2 * 64 + tx * 4);
            ulonglong2 b3 = *(const ulonglong2*)(Ebd + 3 * 64 + tx * 4);
            unsigned long long A[4]  = {a01.x, a01.y, a23.x, a23.y};
            unsigned long long Bv[8] = {b0.x, b0.y, b1.x, b1.y, b2.x, b2.y, b3.x, b3.y};
#pragma unroll
            for (int ip = 0; ip < 4; ++ip)
#pragma unroll
                for (int jc = 0; jc < 8; ++jc) ffma2(acc[ip][jc], A[ip], Bv[jc]);
        }

        // k-tile complete: fold scores into running argmax, reset accumulators
        if ((s & (NDCH - 1)) == NDCH - 1) {
            const int kt = s >> 3;
#pragma unroll
            for (int jc = 0; jc < 8; ++jc) {
                // slot jc = (r, h): r = jc>>1, h = jc&1
                const int code = kt * TN + (jc >> 1) * 32 + tx * 2 + (jc & 1);
#pragma unroll
                for (int ip = 0; ip < 4; ++ip) {
                    float s0 = __uint_as_float((unsigned)(acc[ip][jc] & 0xffffffffull));
                    float s1 = __uint_as_float((unsigned)(acc[ip][jc] >> 32));
                    int t0 = ip * 2, t1 = ip * 2 + 1;
                    if (s0 > bv[t0]) { bv[t0] = s0; bi[t0] = code; }
                    if (s1 > bv[t1]) { bv[t1] = s1; bi[t1] = code; }
                    acc[ip][jc] = 0ull;
                }
            }
        }

        __syncthreads();   // everyone done reading buf^1 before overwrite

        if (s + 1 < NSTAGE) {
#pragma unroll
            for (int r = 0; r < 4; ++r) {
                int f = tid * 4 + r;
                int j = f >> 3;
                int dpos = (f & 7) * 4;
                float* base = Es + ((s + 1) & 1) * (DC * TN * 2);
                float vv[4] = {rg[r].x, rg[r].y, rg[r].z, rg[r].w};
#pragma unroll
                for (int c = 0; c < 4; ++c) {
                    *(float2*)(base + (dpos + c) * (TN * 2) + j * 2) = make_float2(vv[c], vv[c]);
                }
            }
        }
    }

    // ---- cross-thread argmax reduction (reuse Es area) ----
    __syncthreads();
    float* rv = Es;                        // [128][16]
    int*   ri = (int*)(Es + TM * 16);      // [128][16]
    int*   bestcode = (int*)(Es + TM * 16 * 2);  // [128]
#pragma unroll
    for (int t = 0; t < 8; ++t) {
        rv[(ty * 8 + t) * 16 + tx] = bv[t];
        ri[(ty * 8 + t) * 16 + tx] = bi[t];
    }
    __syncthreads();
    if (tid < TM) {
        float best = -3.4e38f;
        int bidx = 0x7fffffff;
#pragma unroll
        for (int j = 0; j < 16; ++j) {
            float v = rv[tid * 16 + j];
            int   c = ri[tid * 16 + j];
            // exact-tie: lowest code index wins (matches jnp.argmax)
            if (v > best || (v == best && c < bidx)) { best = v; bidx = c; }
        }
        bestcode[tid] = bidx;
        long long epos = (long long)NTOK * Dd + (tok0 + tid);
        if (epos < out_size) out[epos] = (float)bidx;   // encoding as float
    }
    __syncthreads();

    // ---- gather raw codewords into quantized output (coalesced) ----
    for (int i = tid; i < TM * (Dd / 4); i += 256) {
        int token = i >> 6;     // 64 float4 per token
        int r = i & 63;
        int code = bestcode[token];
        ((float4*)(out + (size_t)(tok0 + token) * Dd))[r] =
            ((const float4*)(Eqraw + (size_t)code * Dd))[r];
    }
}

// ---------------------------------------------------------------------------
// Tail: zero-fill vq_loss (and any slack) past quantized+encoding.
// ---------------------------------------------------------------------------
__global__ void zero_tail(float* __restrict__ out, long long start, long long end) {
    long long i = start + (long long)blockIdx.x * blockDim.x + threadIdx.x;
    if (i < end) out[i] = 0.f;
}

extern "C" void kernel_launch(void* const* d_in, const int* in_sizes, int n_in,
                              void* d_out, int out_size) {
    const float* x     = (const float*)d_in[0];
    const float* embed = (const float*)d_in[1];
    // robustness: identify inputs by size if order differs
    if (n_in >= 2 && in_sizes[0] == Qn * Kc * Dd && in_sizes[1] == NTOK * Dd) {
        const float* t = x; x = embed; embed = t;
    }
    float* out = (float*)d_out;

    // Normalize embed and x rows with reference-mimicking fp32 pipeline.
    {
        float* en_ptr; cudaGetSymbolAddress((void**)&en_ptr, g_en);
        float* xn_ptr; cudaGetSymbolAddress((void**)&xn_ptr, g_xn);
        l2norm_rows_kernel<<<(Qn * Kc) / 8, 256>>>(embed, en_ptr, Qn * Kc);
        l2norm_rows_kernel<<<NTOK / 8, 256>>>(x, xn_ptr, NTOK);
    }

    // zero_tail writes a disjoint output range; launch it BEFORE pq so the
    // ncu fixed capture slot (-s 5) lands on pq_kernel.
    long long tail = (long long)NTOK * Dd + NTOK;
    if ((long long)out_size > tail) {
        long long n = (long long)out_size - tail;
        int blocks = (int)((n + 255) / 256);
        zero_tail<<<blocks, 256>>>(out, tail, (long long)out_size);
    }

    cudaFuncSetAttribute(pq_kernel, cudaFuncAttributeMaxDynamicSharedMemorySize,
                         SMEM_FLOATS * sizeof(float));

    pq_kernel<<<NTOK / TM, 256, SMEM_FLOATS * sizeof(float)>>>(
        embed, out, (long long)out_size);
}

// round 6
// speedup vs baseline: 2.9849x; 1.2405x over previous
#include <cuda_runtime.h>
#include <cstdint>

// Problem constants
#define Qn 4
#define Kc 2048
#define Dd 256
#define Bb 8
#define Nn 8192
#define NTOK (Bb * Nn)        // 65536 tokens
#define MCHUNK (Nn / Qn)      // 2048 tokens per (b, q) chunk

// Tiling
#define TM 128                // tokens per block
#define TNK 256               // codes per k-tile
#define DC 32                 // d-depth per pipeline stage
#define NKT (Kc / TNK)        // 8 k-tiles
#define NDCH (Dd / DC)        // 8 d-chunks per k-tile
#define NSTAGE (NKT * NDCH)   // 64 stages

// Shared memory layout (floats)
#define XS_FLOATS (Dd * TM)        // 32768 (128 KB)  Xs[d][token]
#define ES_STAGE  (DC * TNK)       // 8192 floats (32 KB) per buffer, natural [dd][code]
#define ES_FLOATS (2 * ES_STAGE)   // 16384 (64 KB), double-buffered
#define SMEM_FLOATS (XS_FLOATS + ES_FLOATS)   // 49152 floats = 192 KB

// Normalized tensors, replicating the reference's fp32 rounding pipeline.
__device__ float g_xn[NTOK * Dd];        // 64 MB, row-major [token][d]
__device__ float g_enT[Qn * Dd * Kc];    // 8 MB, transposed [q][d][code]

// ---------------------------------------------------------------------------
// Kernel 0a: X rows L2-normalized, emulating the reference's fp32 reduce:
//   per-lane partial over [lane + 32*i], UNFUSED mul+add, shfl.down tree,
//   sqrt.rn, max(.,1e-12), div.rn per element.  (DO NOT CHANGE numerics.)
// ---------------------------------------------------------------------------
__global__ void l2norm_x_kernel(const float* __restrict__ src) {
    int row  = blockIdx.x * 8 + (threadIdx.x >> 5);
    int lane = threadIdx.x & 31;
    if (row >= NTOK) return;
    const float* r = src + (size_t)row * Dd;
    float v[8];
    float s = 0.f;
#pragma unroll
    for (int i = 0; i < 8; ++i) {
        v[i] = r[lane + 32 * i];
        s = __fadd_rn(s, __fmul_rn(v[i], v[i]));   // no contraction
    }
#pragma unroll
    for (int o = 16; o; o >>= 1)
        s = __fadd_rn(s, __shfl_down_sync(0xffffffffu, s, o));
    float total = __shfl_sync(0xffffffffu, s, 0);
    float nf = fmaxf(__fsqrt_rn(total), 1e-12f);
    float* w = g_xn + (size_t)row * Dd;
#pragma unroll
    for (int i = 0; i < 8; ++i)
        w[lane + 32 * i] = __fdiv_rn(v[i], nf);
}

// ---------------------------------------------------------------------------
// Kernel 0b: codebook rows normalized with the SAME numerics, stored
// TRANSPOSED: g_enT[q][d][code]  (coalesced staging reads in pq_kernel).
// ---------------------------------------------------------------------------
__global__ void l2norm_e_kernel(const float* __restrict__ embed) {
    int row  = blockIdx.x * 8 + (threadIdx.x >> 5);
    int lane = threadIdx.x & 31;
    if (row >= Qn * Kc) return;
    const float* r = embed + (size_t)row * Dd;
    int q = row >> 11;            // /Kc
    int k = row & (Kc - 1);
    float v[8];
    float s = 0.f;
#pragma unroll
    for (int i = 0; i < 8; ++i) {
        v[i] = r[lane + 32 * i];
        s = __fadd_rn(s, __fmul_rn(v[i], v[i]));
    }
#pragma unroll
    for (int o = 16; o; o >>= 1)
        s = __fadd_rn(s, __shfl_down_sync(0xffffffffu, s, o));
    float total = __shfl_sync(0xffffffffu, s, 0);
    float nf = fmaxf(__fsqrt_rn(total), 1e-12f);
#pragma unroll
    for (int i = 0; i < 8; ++i) {
        int d = lane + 32 * i;
        g_enT[((size_t)q * Dd + d) * Kc + k] = __fdiv_rn(v[i], nf);
    }
}

// Packed fp32x2 FMA: each half rounds identically to scalar FFMA -> the
// per-(token,code) chain stays a sequential ascending-d FFMA chain.
__device__ __forceinline__ void ffma2(unsigned long long& d,
                                      unsigned long long a,
                                      unsigned long long b) {
    asm("fma.rn.f32x2 %0, %1, %2, %0;" : "+l"(d) : "l"(a), "l"(b));
}

// Duplicate one fp32 into both halves of a 64-bit operand (register-side dup).
__device__ __forceinline__ unsigned long long dup2(float v) {
    unsigned long long r;
    asm("mov.b64 %0, {%1, %1};" : "=l"(r) : "r"(__float_as_uint(v)));
    return r;
}

// cp.async helpers
__device__ __forceinline__ void cp16(uint32_t smem_addr, const void* gptr) {
    asm volatile("cp.async.ca.shared.global [%0], [%1], 16;"
                 :: "r"(smem_addr), "l"(gptr));
}
__device__ __forceinline__ void cp_commit() {
    asm volatile("cp.async.commit_group;");
}
template <int N>
__device__ __forceinline__ void cp_wait() {
    asm volatile("cp.async.wait_group %0;" :: "n"(N));
}

// ---------------------------------------------------------------------------
// Kernel 1: fused cosine GEMM + argmax + gather.
// Block = 128 tokens x full 2048 codes (k-tiles of 256), 256 threads.
// Microtile 8 tokens x 16 codes per thread; f32x2 packs ADJACENT CODES
// (natural SMEM pairs), token operand duplicated in registers.
// ---------------------------------------------------------------------------
__global__ void __launch_bounds__(256, 1)
pq_kernel(const float* __restrict__ embed,
          float* __restrict__ out,
          long long out_size) {
    extern __shared__ float smem[];
    float* Xs = smem;                 // [256][128]  xn[d][token]
    float* Es = smem + XS_FLOATS;     // [2][32][256] natural [dd][code]

    const int tid = threadIdx.x;
    const int tx  = tid & 15;           // code group: codes r*64 + tx*4 + c
    const int ty  = tid >> 4;           // token group: tokens ty*8 .. +8
    const int tok0 = blockIdx.x * TM;
    const int q = (tok0 % Nn) / MCHUNK;
    const float* EqT   = g_enT  + (size_t)q * Dd * Kc;  // normalized, transposed
    const float* Eqraw = embed  + (size_t)q * Kc * Dd;  // raw, for gather

    // staging assignment for Es: thread covers one dd row, 32 codes (128B)
    const int sdd = tid >> 3;                 // 0..31
    const int sc0 = (tid & 7) * 32;           // 0..224
    const uint32_t es_base = (uint32_t)__cvta_generic_to_shared(Es);

    // issue stage-0 cp.async immediately (overlaps X staging)
    {
        const float* src = EqT + (size_t)sdd * Kc + sc0;   // kt=0, dc=0
        uint32_t dst = es_base + (uint32_t)(sdd * TNK + sc0) * 4u;
#pragma unroll
        for (int u = 0; u < 8; ++u) cp16(dst + u * 16u, src + u * 4);
        cp_commit();
    }

    // stage normalized X tile transposed: Xs[d][token]
    for (int i = tid; i < TM * (Dd / 4); i += 256) {
        int token = i & (TM - 1);
        int rb    = i >> 7;            // float4 index along d: 0..63
        float4 v = ((const float4*)(g_xn + (size_t)(tok0 + token) * Dd))[rb];
        Xs[(rb * 4 + 0) * TM + token] = v.x;
        Xs[(rb * 4 + 1) * TM + token] = v.y;
        Xs[(rb * 4 + 2) * TM + token] = v.z;
        Xs[(rb * 4 + 3) * TM + token] = v.w;
    }

    // accumulators: 8 tokens x 8 code-pairs, packed f32x2 (adjacent codes)
    unsigned long long acc[8][8];
#pragma unroll
    for (int t = 0; t < 8; ++t)
#pragma unroll
        for (int cp = 0; cp < 8; ++cp) acc[t][cp] = 0ull;

    // per-token argmax (codes visited ascending; strict > keeps lowest index)
    float bv[8];
    int   bi[8];
#pragma unroll
    for (int t = 0; t < 8; ++t) { bv[t] = -3.4e38f; bi[t] = 0x7fffffff; }

    for (int s = 0; s < NSTAGE; ++s) {
        __syncthreads();   // all warps done computing on buf (s+1)&1 from s-1
                           // (s=0: X staging complete)

        // issue cp.async for stage s+1 into buf (s+1)&1
        if (s + 1 < NSTAGE) {
            const int kt = (s + 1) >> 3;
            const int dc = (s + 1) & (NDCH - 1);
            const float* src = EqT + (size_t)(dc * DC + sdd) * Kc + kt * TNK + sc0;
            uint32_t dst = es_base +
                (uint32_t)(((s + 1) & 1) * ES_STAGE + sdd * TNK + sc0) * 4u;
#pragma unroll
            for (int u = 0; u < 8; ++u) cp16(dst + u * 16u, src + u * 4);
            cp_commit();
            cp_wait<1>();   // stage s landed (own thread)
        } else {
            cp_wait<0>();
        }

        __syncthreads();   // stage s visible block-wide

        // compute 32 d-steps from buf s&1 (ascending d => sequential chain)
        const int dcBase = (s & (NDCH - 1)) * DC;
        const float* Eb = Es + (s & 1) * ES_STAGE;
#pragma unroll 8
        for (int dd = 0; dd < DC; ++dd) {
            const int dg = dcBase + dd;
            float4 xa = *(const float4*)&Xs[dg * TM + ty * 8];
            float4 xb = *(const float4*)&Xs[dg * TM + ty * 8 + 4];
            const float* Ebd = Eb + dd * TNK;
            // natural adjacent-code pairs: b_r = codes (r*64+tx*4 .. +3)
            ulonglong2 b0 = *(const ulonglong2*)(Ebd + 0 * 64 + tx * 4);
            ulonglong2 b1 = *(const ulonglong2*)(Ebd + 1 * 64 + tx * 4);
            ulonglong2 b2 = *(const ulonglong2*)(Ebd + 2 * 64 + tx * 4);
            ulonglong2 b3 = *(const ulonglong2*)(Ebd + 3 * 64 + tx * 4);
            unsigned long long Bv[8] = {b0.x, b0.y, b1.x, b1.y,
                                        b2.x, b2.y, b3.x, b3.y};
            float Af[8] = {xa.x, xa.y, xa.z, xa.w, xb.x, xb.y, xb.z, xb.w};
#pragma unroll
            for (int t = 0; t < 8; ++t) {
                unsigned long long At = dup2(Af[t]);
#pragma unroll
                for (int cp = 0; cp < 8; ++cp) ffma2(acc[t][cp], At, Bv[cp]);
            }
        }

        // k-tile complete: fold into running argmax, reset accumulators
        if ((s & (NDCH - 1)) == NDCH - 1) {
            const int kt = s >> 3;
#pragma unroll
            for (int cp = 0; cp < 8; ++cp) {
                const int code = kt * TNK + (cp >> 1) * 64 + tx * 4 + (cp & 1) * 2;
#pragma unroll
                for (int t = 0; t < 8; ++t) {
                    float lo = __uint_as_float((unsigned)(acc[t][cp] & 0xffffffffull));
                    float hi = __uint_as_float((unsigned)(acc[t][cp] >> 32));
                    if (lo > bv[t]) { bv[t] = lo; bi[t] = code; }
                    if (hi > bv[t]) { bv[t] = hi; bi[t] = code + 1; }
                    acc[t][cp] = 0ull;
                }
            }
        }
    }

    // ---- cross-thread argmax reduction (reuse Es area) ----
    __syncthreads();
    float* rv = Es;                        // [128][16]
    int*   ri = (int*)(Es + TM * 16);      // [128][16]
    int*   bestcode = (int*)(Es + TM * 16 * 2);  // [128]
#pragma unroll
    for (int t = 0; t < 8; ++t) {
        rv[(ty * 8 + t) * 16 + tx] = bv[t];
        ri[(ty * 8 + t) * 16 + tx] = bi[t];
    }
    __syncthreads();
    if (tid < TM) {
        float best = -3.4e38f;
        int bidx = 0x7fffffff;
#pragma unroll
        for (int j = 0; j < 16; ++j) {
            float v = rv[tid * 16 + j];
            int   c = ri[tid * 16 + j];
            // exact-tie: lowest code index wins (matches jnp.argmax)
            if (v > best || (v == best && c < bidx)) { best = v; bidx = c; }
        }
        bestcode[tid] = bidx;
        long long epos = (long long)NTOK * Dd + (tok0 + tid);
        if (epos < out_size) out[epos] = (float)bidx;   // encoding as float
    }
    __syncthreads();

    // ---- gather raw codewords into quantized output (coalesced) ----
    for (int i = tid; i < TM * (Dd / 4); i += 256) {
        int token = i >> 6;     // 64 float4 per token
        int r = i & 63;
        int code = bestcode[token];
        ((float4*)(out + (size_t)(tok0 + token) * Dd))[r] =
            ((const float4*)(Eqraw + (size_t)code * Dd))[r];
    }
}

// ---------------------------------------------------------------------------
// Tail: zero-fill vq_loss (and any slack) past quantized+encoding.
// ---------------------------------------------------------------------------
__global__ void zero_tail(float* __restrict__ out, long long start, long long end) {
    long long i = start + (long long)blockIdx.x * blockDim.x + threadIdx.x;
    if (i < end) out[i] = 0.f;
}

extern "C" void kernel_launch(void* const* d_in, const int* in_sizes, int n_in,
                              void* d_out, int out_size) {
    const float* x     = (const float*)d_in[0];
    const float* embed = (const float*)d_in[1];
    // robustness: identify inputs by size if order differs
    if (n_in >= 2 && in_sizes[0] == Qn * Kc * Dd && in_sizes[1] == NTOK * Dd) {
        const float* t = x; x = embed; embed = t;
    }
    float* out = (float*)d_out;

    l2norm_e_kernel<<<(Qn * Kc) / 8, 256>>>(embed);
    l2norm_x_kernel<<<NTOK / 8, 256>>>(x);

    // zero_tail writes a disjoint range; launch BEFORE pq so the ncu fixed
    // capture slot lands on pq_kernel.
    long long tail = (long long)NTOK * Dd + NTOK;
    if ((long long)out_size > tail) {
        long long n = (long long)out_size - tail;
        int blocks = (int)((n + 255) / 256);
        zero_tail<<<blocks, 256>>>(out, tail, (long long)out_size);
    }

    cudaFuncSetAttribute(pq_kernel, cudaFuncAttributeMaxDynamicSharedMemorySize,
                         SMEM_FLOATS * sizeof(float));

    pq_kernel<<<NTOK / TM, 256, SMEM_FLOATS * sizeof(float)>>>(
        embed, out, (long long)out_size);
}